// round 5
// baseline (speedup 1.0000x reference)
#include <cuda_runtime.h>
#include <math_constants.h>
#include <cstdint>

// ---------------------------------------------------------------------------
// PointNetConv via mma.sync tf32 (3-term split => fp32-grade accuracy)
//   3x (1x1 conv -> BN(train) -> ReLU) -> max over K=64 neighbors
//   L0: 67->64 (K=64 MMA + 3 scalar epilogue channels), L1: 64->64, L2: 64->128
// CTA: 256 thr / 8 warps, tile 128 rows x 64 cols. Warp tile 32x32
// (2 m-tiles x 4 n-tiles of m16n8k8). A/B stored in smem as interleaved
// (tf32_hi, tf32_lo) uint2 pairs, pair-stride 68 (bank-conflict-free frags).
// Accumulate fp32 in registers; epilogue fuses bias, BN stats partials and
// (L2) per-node max/min so conv2 output is never materialized.
// ---------------------------------------------------------------------------

#define TOTAL_ROWS (16384 * 64)
#define NBLK       8192
#define NNODES     16384
#define EPS        1e-5f
#define PCOUNT     ((float)TOTAL_ROWS)

__device__ float g_h0[TOTAL_ROWS * 64];
__device__ float g_h1[TOTAL_ROWS * 64];
__device__ float g_mx[NNODES * 128];
__device__ float g_mn[NNODES * 128];
__device__ float g_psum[128 * NBLK];
__device__ float g_psq [128 * NBLK];
__device__ float g_bna[128];
__device__ float g_bnc[128];

// ---- smem byte offsets ----
#define SM_BIAS   0                      // 64 f
#define SM_BA     256                    // 64 f
#define SM_BC     512                    // 64 f
#define SM_WE     768                    // 64*4 f
#define SM_XE     1792                   // 128*4 f
#define SM_PS     3840                   // 4*64 f
#define SM_PQ     4864                   // 4*64 f
#define SM_MX     5888                   // 4*64 f
#define SM_MN     6912                   // 4*64 f
#define SM_A      8192                   // 128*68 uint2 = 69632 B
#define SM_B      (8192 + 69632)         // 64*68 uint2 = 34816 B
#define SM_TOTAL  (8192 + 69632 + 34816) // 112640 B

static __device__ __forceinline__ void split_tf32(float v, uint32_t& hi, uint32_t& lo) {
    asm("cvt.rna.tf32.f32 %0, %1;" : "=r"(hi) : "f"(v));
    float r = v - __uint_as_float(hi);   // exact (hi has shorter mantissa)
    asm("cvt.rna.tf32.f32 %0, %1;" : "=r"(lo) : "f"(r));
}

static __device__ __forceinline__ void mma_tf32(float* c, const uint32_t* a,
                                                const uint32_t* b) {
    asm volatile(
        "mma.sync.aligned.m16n8k8.row.col.f32.tf32.tf32.f32 "
        "{%0,%1,%2,%3}, {%4,%5,%6,%7}, {%8,%9}, {%0,%1,%2,%3};"
        : "+f"(c[0]), "+f"(c[1]), "+f"(c[2]), "+f"(c[3])
        : "r"(a[0]), "r"(a[1]), "r"(a[2]), "r"(a[3]), "r"(b[0]), "r"(b[1]));
}

// ---------------------------------------------------------------------------
template <int CIN, bool BN_IN, bool REDUCE>
__global__ void __launch_bounds__(256) gemm_mma(
    const float* __restrict__ X, const float* __restrict__ W,
    const float* __restrict__ B,
    const float* __restrict__ bna, const float* __restrict__ bnc,
    float* __restrict__ H, float* __restrict__ mxout, float* __restrict__ mnout,
    float* __restrict__ psum, float* __restrict__ psq)
{
    extern __shared__ char smem[];
    float* Bs = (float*)(smem + SM_BIAS);
    float* Ba = (float*)(smem + SM_BA);
    float* Bc = (float*)(smem + SM_BC);
    float* We = (float*)(smem + SM_WE);
    float* Xe = (float*)(smem + SM_XE);
    float* Ps = (float*)(smem + SM_PS);
    float* Pq = (float*)(smem + SM_PQ);
    float* Mxs = (float*)(smem + SM_MX);
    float* Mns = (float*)(smem + SM_MN);
    uint2* Ap = (uint2*)(smem + SM_A);   // [128][68] (hi,lo)
    uint2* Bp = (uint2*)(smem + SM_B);   // [64][68]  (hi,lo)

    const int tid = threadIdx.x;
    const int wid = tid >> 5;
    const int lane = tid & 31;
    const int q = lane >> 2, s = lane & 3;
    const int bx = blockIdx.x;
    const int ob = blockIdx.y * 64;
    const long long row0 = (long long)bx * 128;

    // ---- params ----
    if (tid < 64) Bs[tid] = B[ob + tid];
    if (BN_IN && tid >= 64 && tid < 128) {
        Ba[tid - 64] = bna[tid - 64];
        Bc[tid - 64] = bnc[tid - 64];
    }
    if (BN_IN) __syncthreads();

    // ---- W -> Bp pairs ----
    for (int p = tid; p < 64 * 64; p += 256) {
        int o = p >> 6, c = p & 63;
        uint32_t h, l; split_tf32(W[(ob + o) * CIN + c], h, l);
        Bp[o * 68 + c] = make_uint2(h, l);
    }
    // ---- X -> Ap pairs (BN+ReLU on load) ----
    for (int p = tid; p < 128 * 64; p += 256) {
        int r = p >> 6, c = p & 63;
        float v = X[(row0 + r) * CIN + c];
        if (BN_IN) v = fmaxf(fmaf(Ba[c], v, Bc[c]), 0.0f);
        uint32_t h, l; split_tf32(v, h, l);
        Ap[r * 68 + c] = make_uint2(h, l);
    }
    if (CIN == 67) {
        for (int p = tid; p < 64 * 4; p += 256) {
            int o = p >> 2, j = p & 3;
            We[p] = (j < 3) ? W[(ob + o) * 67 + 64 + j] : 0.0f;
        }
        for (int p = tid; p < 128 * 4; p += 256) {
            int r = p >> 2, j = p & 3;
            Xe[p] = (j < 3) ? X[(row0 + r) * 67 + 64 + j] : 0.0f;
        }
    }
    __syncthreads();

    // ---- MMA mainloop: warp tile 32x32, K=64 in 8 steps ----
    const int wr = (wid >> 1) * 32;
    const int wc = (wid & 1) * 32;

    float acc[8][4];
#pragma unroll
    for (int t = 0; t < 8; t++)
#pragma unroll
        for (int j = 0; j < 4; j++) acc[t][j] = 0.0f;

#pragma unroll
    for (int k8 = 0; k8 < 64; k8 += 8) {
        uint32_t ah[2][4], al[2][4];
#pragma unroll
        for (int mt = 0; mt < 2; mt++) {
            int r0 = wr + mt * 16 + q;
            uint2 p00 = Ap[(r0    ) * 68 + k8 + s];
            uint2 p10 = Ap[(r0 + 8) * 68 + k8 + s];
            uint2 p01 = Ap[(r0    ) * 68 + k8 + s + 4];
            uint2 p11 = Ap[(r0 + 8) * 68 + k8 + s + 4];
            ah[mt][0] = p00.x; al[mt][0] = p00.y;
            ah[mt][1] = p10.x; al[mt][1] = p10.y;
            ah[mt][2] = p01.x; al[mt][2] = p01.y;
            ah[mt][3] = p11.x; al[mt][3] = p11.y;
        }
#pragma unroll
        for (int nt = 0; nt < 4; nt++) {
            int n = wc + nt * 8 + q;
            uint2 pb0 = Bp[n * 68 + k8 + s];
            uint2 pb1 = Bp[n * 68 + k8 + s + 4];
            uint32_t bh[2] = {pb0.x, pb1.x};
            uint32_t bl[2] = {pb0.y, pb1.y};
#pragma unroll
            for (int mt = 0; mt < 2; mt++) {
                mma_tf32(acc[mt * 4 + nt], ah[mt], bh);
                mma_tf32(acc[mt * 4 + nt], al[mt], bh);
                mma_tf32(acc[mt * 4 + nt], ah[mt], bl);
            }
        }
    }

    // ---- epilogue: bias (+L0 extra channels), stats, max/min, H store ----
    float ps[8], pq[8], mxv[8], mnv[8];
#pragma unroll
    for (int t = 0; t < 8; t++) {
        ps[t] = 0.0f; pq[t] = 0.0f;
        mxv[t] = -CUDART_INF_F; mnv[t] = CUDART_INF_F;
    }

#pragma unroll
    for (int mt = 0; mt < 2; mt++) {
#pragma unroll
        for (int h = 0; h < 2; h++) {
            int r = wr + mt * 16 + q + h * 8;
            float4 xe = make_float4(0.f, 0.f, 0.f, 0.f);
            if (CIN == 67) xe = *(float4*)&Xe[r * 4];
#pragma unroll
            for (int nt = 0; nt < 4; nt++) {
                int cb = wc + nt * 8 + 2 * s;
                float v0 = acc[mt * 4 + nt][h * 2 + 0] + Bs[cb];
                float v1 = acc[mt * 4 + nt][h * 2 + 1] + Bs[cb + 1];
                if (CIN == 67) {
                    float4 w0 = *(float4*)&We[cb * 4];
                    float4 w1 = *(float4*)&We[(cb + 1) * 4];
                    v0 += w0.x * xe.x + w0.y * xe.y + w0.z * xe.z;
                    v1 += w1.x * xe.x + w1.y * xe.y + w1.z * xe.z;
                }
                if (!REDUCE)
                    *(float2*)&H[(row0 + r) * 64 + cb] = make_float2(v0, v1);
                int t0 = nt * 2, t1 = nt * 2 + 1;
                ps[t0] += v0; pq[t0] += v0 * v0;
                ps[t1] += v1; pq[t1] += v1 * v1;
                if (REDUCE) {
                    mxv[t0] = fmaxf(mxv[t0], v0); mnv[t0] = fminf(mnv[t0], v0);
                    mxv[t1] = fmaxf(mxv[t1], v1); mnv[t1] = fminf(mnv[t1], v1);
                }
            }
        }
    }

    // warp reduce over q (lanes sharing same s): offsets 16, 8, 4
#pragma unroll
    for (int off = 16; off >= 4; off >>= 1) {
#pragma unroll
        for (int t = 0; t < 8; t++) {
            ps[t] += __shfl_down_sync(0xffffffffu, ps[t], off);
            pq[t] += __shfl_down_sync(0xffffffffu, pq[t], off);
            if (REDUCE) {
                mxv[t] = fmaxf(mxv[t], __shfl_down_sync(0xffffffffu, mxv[t], off));
                mnv[t] = fminf(mnv[t], __shfl_down_sync(0xffffffffu, mnv[t], off));
            }
        }
    }
    const int wr_idx = wid >> 1;
    if (q == 0) {   // lanes 0..3 hold totals; s = lane
#pragma unroll
        for (int t = 0; t < 8; t++) {
            int c = wc + (t >> 1) * 8 + 2 * s + (t & 1);
            Ps[wr_idx * 64 + c] = ps[t];
            Pq[wr_idx * 64 + c] = pq[t];
            if (REDUCE) {
                Mxs[wr_idx * 64 + c] = mxv[t];
                Mns[wr_idx * 64 + c] = mnv[t];
            }
        }
    }
    __syncthreads();

    if (tid < 64) {
        float sa = Ps[tid] + Ps[64 + tid] + Ps[128 + tid] + Ps[192 + tid];
        float qa = Pq[tid] + Pq[64 + tid] + Pq[128 + tid] + Pq[192 + tid];
        psum[(ob + tid) * NBLK + bx] = sa;
        psq [(ob + tid) * NBLK + bx] = qa;
    }
    if (REDUCE && tid < 128) {
        int half = tid >> 6, c = tid & 63;     // half 0 -> rows 0..63 (node A)
        float mx = fmaxf(Mxs[(half * 2) * 64 + c], Mxs[(half * 2 + 1) * 64 + c]);
        float mn = fminf(Mns[(half * 2) * 64 + c], Mns[(half * 2 + 1) * 64 + c]);
        int node = bx * 2 + half;
        mxout[node * 128 + ob + c] = mx;
        mnout[node * 128 + ob + c] = mn;
    }
}

// ---------------------------------------------------------------------------
__global__ void __launch_bounds__(256) stats_finalize(
    const float* __restrict__ psum, const float* __restrict__ psq,
    const float* __restrict__ gamma, const float* __restrict__ beta,
    float* __restrict__ bna, float* __restrict__ bnc)
{
    const int o = blockIdx.x;
    const int tid = threadIdx.x;
    float s = 0.0f, q = 0.0f;
    for (int b = tid; b < NBLK; b += 256) {
        s += psum[o * NBLK + b];
        q += psq [o * NBLK + b];
    }
    __shared__ float sh[512];
    sh[tid] = s; sh[256 + tid] = q;
    __syncthreads();
    for (int st = 128; st > 0; st >>= 1) {
        if (tid < st) {
            sh[tid]       += sh[tid + st];
            sh[256 + tid] += sh[256 + tid + st];
        }
        __syncthreads();
    }
    if (tid == 0) {
        float mean = sh[0] / PCOUNT;
        float var  = sh[256] / PCOUNT - mean * mean;
        float a    = gamma[o] * rsqrtf(var + EPS);
        bna[o] = a;
        bnc[o] = beta[o] - mean * a;
    }
}

__global__ void __launch_bounds__(256) apply_out(
    const float* __restrict__ mx, const float* __restrict__ mn,
    const float* __restrict__ bna, const float* __restrict__ bnc,
    float* __restrict__ out)
{
    int idx = blockIdx.x * 256 + threadIdx.x;
    int c = idx & 127;
    float a = bna[c];
    float h = (a > 0.0f) ? mx[idx] : mn[idx];
    out[idx] = fmaxf(fmaf(a, h, bnc[c]), 0.0f);
}

// ---------------------------------------------------------------------------
extern "C" void kernel_launch(void* const* d_in, const int* in_sizes, int n_in,
                              void* d_out, int out_size)
{
    const float* x   = (const float*)d_in[0];
    const float* w0  = (const float*)d_in[1];
    const float* b0  = (const float*)d_in[2];
    const float* gm0 = (const float*)d_in[3];
    const float* be0 = (const float*)d_in[4];
    const float* w1  = (const float*)d_in[5];
    const float* b1  = (const float*)d_in[6];
    const float* gm1 = (const float*)d_in[7];
    const float* be1 = (const float*)d_in[8];
    const float* w2  = (const float*)d_in[9];
    const float* b2  = (const float*)d_in[10];
    const float* gm2 = (const float*)d_in[11];
    const float* be2 = (const float*)d_in[12];
    float* out = (float*)d_out;

    float *h0, *h1, *mx, *mn, *psum, *psq, *bna, *bnc;
    cudaGetSymbolAddress((void**)&h0,   g_h0);
    cudaGetSymbolAddress((void**)&h1,   g_h1);
    cudaGetSymbolAddress((void**)&mx,   g_mx);
    cudaGetSymbolAddress((void**)&mn,   g_mn);
    cudaGetSymbolAddress((void**)&psum, g_psum);
    cudaGetSymbolAddress((void**)&psq,  g_psq);
    cudaGetSymbolAddress((void**)&bna,  g_bna);
    cudaGetSymbolAddress((void**)&bnc,  g_bnc);

    cudaFuncSetAttribute(gemm_mma<67, false, false>,
                         cudaFuncAttributeMaxDynamicSharedMemorySize, SM_TOTAL);
    cudaFuncSetAttribute(gemm_mma<64, true, false>,
                         cudaFuncAttributeMaxDynamicSharedMemorySize, SM_TOTAL);
    cudaFuncSetAttribute(gemm_mma<64, true, true>,
                         cudaFuncAttributeMaxDynamicSharedMemorySize, SM_TOTAL);

    // L0: conv(67->64) + stats
    gemm_mma<67, false, false><<<dim3(NBLK, 1), 256, SM_TOTAL>>>(
        x, w0, b0, nullptr, nullptr, h0, nullptr, nullptr, psum, psq);
    stats_finalize<<<64, 256>>>(psum, psq, gm0, be0, bna, bnc);

    // L1: bn0+relu on load -> conv(64->64) + stats
    gemm_mma<64, true, false><<<dim3(NBLK, 1), 256, SM_TOTAL>>>(
        h0, w1, b1, bna, bnc, h1, nullptr, nullptr, psum, psq);
    stats_finalize<<<64, 256>>>(psum, psq, gm1, be1, bna, bnc);

    // L2: bn1+relu on load -> conv(64->128 in two N-halves) + stats
    //     + fused per-node max/min (no H2 materialization)
    gemm_mma<64, true, true><<<dim3(NBLK, 2), 256, SM_TOTAL>>>(
        h1, w2, b2, bna, bnc, nullptr, mx, mn, psum, psq);
    stats_finalize<<<128, 256>>>(psum, psq, gm2, be2, bna, bnc);

    apply_out<<<(NNODES * 128) / 256, 256>>>(mx, mn, bna, bnc, out);
}

// round 6
// speedup vs baseline: 1.3498x; 1.3498x over previous
#include <cuda_runtime.h>
#include <cuda_bf16.h>
#include <math_constants.h>
#include <cstdint>

// ---------------------------------------------------------------------------
// PointNetConv via mma.sync bf16 m16n8k16, 3-term split (~1e-5 accuracy)
//   3x (1x1 conv -> BN(train) -> ReLU) -> max over K=64 neighbors
//   L0: 67->64 (K=64 MMA + 3 exact scalar epilogue channels), L1: 64->64,
//   L2: 64->128 (two N-halves, fused per-node max/min, no H2 materialization)
// CTA: 256 thr / 8 warps, tile 128 rows x 64 cols. Warp tile 32x32
// (2 m-tiles x 4 n-tiles of m16n8k16). A/B in smem as interleaved
// (bf16x2_hi, bf16x2_lo) uint2 k-pairs; one LDS.64 feeds hi+lo terms.
// A stride 34 uint2 (272B), B stride 36 uint2 (288B, conflict-free).
// ---------------------------------------------------------------------------

#define TOTAL_ROWS (16384 * 64)
#define NBLK       8192
#define NNODES     16384
#define EPS        1e-5f
#define PCOUNT     ((float)TOTAL_ROWS)

__device__ float g_h0[TOTAL_ROWS * 64];
__device__ float g_h1[TOTAL_ROWS * 64];
__device__ float g_mx[NNODES * 128];
__device__ float g_mn[NNODES * 128];
__device__ float g_psum[128 * NBLK];
__device__ float g_psq [128 * NBLK];
__device__ float g_bna[128];
__device__ float g_bnc[128];

// ---- smem byte offsets ----
#define SM_BIAS   0
#define SM_BA     256
#define SM_BC     512
#define SM_WE     768
#define SM_XE     1792
#define SM_PS     3840
#define SM_PQ     4864
#define SM_MX     5888
#define SM_MN     6912
#define SM_A      8192                    // 128*34 uint2 = 34816 B
#define SM_B      (8192 + 34816)          // 64*36 uint2  = 18432 B
#define SM_TOTAL  (8192 + 34816 + 18432)  // 61440 B -> 3 CTAs/SM

#define AS 34   // A pair-stride (uint2)
#define BS 36   // B pair-stride (uint2)

// split two fp32 (k-even, k-odd) into packed bf16x2 hi and lo words
static __device__ __forceinline__ uint2 split2_bf16(float v0, float v1) {
    __nv_bfloat16 h0 = __float2bfloat16_rn(v0);
    __nv_bfloat16 h1 = __float2bfloat16_rn(v1);
    float r0 = v0 - __bfloat162float(h0);
    float r1 = v1 - __bfloat162float(h1);
    __nv_bfloat16 l0 = __float2bfloat16_rn(r0);
    __nv_bfloat16 l1 = __float2bfloat16_rn(r1);
    uint32_t hi = (uint32_t)__bfloat16_as_ushort(h0) |
                  ((uint32_t)__bfloat16_as_ushort(h1) << 16);
    uint32_t lo = (uint32_t)__bfloat16_as_ushort(l0) |
                  ((uint32_t)__bfloat16_as_ushort(l1) << 16);
    return make_uint2(hi, lo);
}

static __device__ __forceinline__ void mma_bf16(float* c, const uint32_t* a,
                                                const uint32_t* b) {
    asm volatile(
        "mma.sync.aligned.m16n8k16.row.col.f32.bf16.bf16.f32 "
        "{%0,%1,%2,%3}, {%4,%5,%6,%7}, {%8,%9}, {%0,%1,%2,%3};"
        : "+f"(c[0]), "+f"(c[1]), "+f"(c[2]), "+f"(c[3])
        : "r"(a[0]), "r"(a[1]), "r"(a[2]), "r"(a[3]), "r"(b[0]), "r"(b[1]));
}

// ---------------------------------------------------------------------------
template <int CIN, bool BN_IN, bool REDUCE>
__global__ void __launch_bounds__(256, 3) gemm_mma(
    const float* __restrict__ X, const float* __restrict__ W,
    const float* __restrict__ B,
    const float* __restrict__ bna, const float* __restrict__ bnc,
    float* __restrict__ H, float* __restrict__ mxout, float* __restrict__ mnout,
    float* __restrict__ psum, float* __restrict__ psq)
{
    extern __shared__ char smem[];
    float* Bsm = (float*)(smem + SM_BIAS);
    float* Ba  = (float*)(smem + SM_BA);
    float* Bc  = (float*)(smem + SM_BC);
    float* We  = (float*)(smem + SM_WE);
    float* Xe  = (float*)(smem + SM_XE);
    float* Ps  = (float*)(smem + SM_PS);
    float* Pq  = (float*)(smem + SM_PQ);
    float* Mxs = (float*)(smem + SM_MX);
    float* Mns = (float*)(smem + SM_MN);
    uint2* Ap  = (uint2*)(smem + SM_A);   // [128][AS] (hiPair, loPair)
    uint2* Bp  = (uint2*)(smem + SM_B);   // [64][BS]

    const int tid  = threadIdx.x;
    const int wid  = tid >> 5;
    const int lane = tid & 31;
    const int q = lane >> 2, s = lane & 3;
    const int bx = blockIdx.x;
    const int ob = blockIdx.y * 64;
    const long long row0 = (long long)bx * 128;

    if (tid < 64) Bsm[tid] = B[ob + tid];
    if (BN_IN && tid >= 64 && tid < 128) {
        Ba[tid - 64] = bna[tid - 64];
        Bc[tid - 64] = bnc[tid - 64];
    }
    if (BN_IN) __syncthreads();

    // ---- W -> Bp pairs (col n, k-pair pr) ----
    for (int p = tid; p < 64 * 32; p += 256) {
        int n = p >> 5, pr = p & 31;
        float v0 = W[(ob + n) * CIN + 2 * pr];
        float v1 = W[(ob + n) * CIN + 2 * pr + 1];
        Bp[n * BS + pr] = split2_bf16(v0, v1);
    }
    // ---- X -> Ap pairs (BN+ReLU on load) ----
    for (int p = tid; p < 128 * 32; p += 256) {
        int r = p >> 5, pr = p & 31;
        float v0, v1;
        if (CIN == 64) {
            float2 v = *(const float2*)&X[(row0 + r) * 64 + 2 * pr];
            v0 = v.x; v1 = v.y;
        } else {
            v0 = X[(row0 + r) * CIN + 2 * pr];
            v1 = X[(row0 + r) * CIN + 2 * pr + 1];
        }
        if (BN_IN) {
            v0 = fmaxf(fmaf(Ba[2 * pr], v0, Bc[2 * pr]), 0.0f);
            v1 = fmaxf(fmaf(Ba[2 * pr + 1], v1, Bc[2 * pr + 1]), 0.0f);
        }
        Ap[r * AS + pr] = split2_bf16(v0, v1);
    }
    if (CIN == 67) {
        for (int p = tid; p < 64 * 4; p += 256) {
            int o = p >> 2, j = p & 3;
            We[p] = (j < 3) ? W[(ob + o) * 67 + 64 + j] : 0.0f;
        }
        for (int p = tid; p < 128 * 4; p += 256) {
            int r = p >> 2, j = p & 3;
            Xe[p] = (j < 3) ? X[(row0 + r) * 67 + 64 + j] : 0.0f;
        }
    }
    __syncthreads();

    // ---- MMA mainloop: warp tile 32x32, K=64 in 4 k16-steps ----
    const int wr = (wid >> 1) * 32;
    const int wc = (wid & 1) * 32;

    float acc[8][4];
#pragma unroll
    for (int t = 0; t < 8; t++)
#pragma unroll
        for (int j = 0; j < 4; j++) acc[t][j] = 0.0f;

#pragma unroll
    for (int kk = 0; kk < 4; kk++) {
        const int pb = kk * 8 + s;
        uint32_t ah[2][4], al[2][4];
#pragma unroll
        for (int mt = 0; mt < 2; mt++) {
            int r0 = wr + mt * 16 + q;
            uint2 a0 = Ap[(r0    ) * AS + pb];      // k=2s,2s+1
            uint2 a1 = Ap[(r0 + 8) * AS + pb];
            uint2 a2 = Ap[(r0    ) * AS + pb + 4];  // k=2s+8,2s+9
            uint2 a3 = Ap[(r0 + 8) * AS + pb + 4];
            ah[mt][0] = a0.x; al[mt][0] = a0.y;
            ah[mt][1] = a1.x; al[mt][1] = a1.y;
            ah[mt][2] = a2.x; al[mt][2] = a2.y;
            ah[mt][3] = a3.x; al[mt][3] = a3.y;
        }
#pragma unroll
        for (int nt = 0; nt < 4; nt++) {
            int n = wc + nt * 8 + q;
            uint2 b0 = Bp[n * BS + pb];
            uint2 b1 = Bp[n * BS + pb + 4];
            uint32_t bh[2] = {b0.x, b1.x};
            uint32_t bl[2] = {b0.y, b1.y};
#pragma unroll
            for (int mt = 0; mt < 2; mt++) {
                mma_bf16(acc[mt * 4 + nt], ah[mt], bh);
                mma_bf16(acc[mt * 4 + nt], al[mt], bh);
                mma_bf16(acc[mt * 4 + nt], ah[mt], bl);
            }
        }
    }

    // ---- epilogue: bias (+L0 exact extra channels), stats, max/min ----
    float ps[8], pq[8], mxv[8], mnv[8];
#pragma unroll
    for (int t = 0; t < 8; t++) {
        ps[t] = 0.0f; pq[t] = 0.0f;
        mxv[t] = -CUDART_INF_F; mnv[t] = CUDART_INF_F;
    }

#pragma unroll
    for (int mt = 0; mt < 2; mt++) {
#pragma unroll
        for (int h = 0; h < 2; h++) {
            int r = wr + mt * 16 + q + h * 8;
            float4 xe = make_float4(0.f, 0.f, 0.f, 0.f);
            if (CIN == 67) xe = *(float4*)&Xe[r * 4];
#pragma unroll
            for (int nt = 0; nt < 4; nt++) {
                int cb = wc + nt * 8 + 2 * s;
                float v0 = acc[mt * 4 + nt][h * 2 + 0] + Bsm[cb];
                float v1 = acc[mt * 4 + nt][h * 2 + 1] + Bsm[cb + 1];
                if (CIN == 67) {
                    float4 w0 = *(float4*)&We[cb * 4];
                    float4 w1 = *(float4*)&We[(cb + 1) * 4];
                    v0 += w0.x * xe.x + w0.y * xe.y + w0.z * xe.z;
                    v1 += w1.x * xe.x + w1.y * xe.y + w1.z * xe.z;
                }
                if (!REDUCE)
                    *(float2*)&H[(row0 + r) * 64 + cb] = make_float2(v0, v1);
                int t0 = nt * 2, t1 = nt * 2 + 1;
                ps[t0] += v0; pq[t0] += v0 * v0;
                ps[t1] += v1; pq[t1] += v1 * v1;
                if (REDUCE) {
                    mxv[t0] = fmaxf(mxv[t0], v0); mnv[t0] = fminf(mnv[t0], v0);
                    mxv[t1] = fmaxf(mxv[t1], v1); mnv[t1] = fminf(mnv[t1], v1);
                }
            }
        }
    }

    // warp reduce over q (offsets 16, 8, 4)
#pragma unroll
    for (int off = 16; off >= 4; off >>= 1) {
#pragma unroll
        for (int t = 0; t < 8; t++) {
            ps[t] += __shfl_down_sync(0xffffffffu, ps[t], off);
            pq[t] += __shfl_down_sync(0xffffffffu, pq[t], off);
            if (REDUCE) {
                mxv[t] = fmaxf(mxv[t], __shfl_down_sync(0xffffffffu, mxv[t], off));
                mnv[t] = fminf(mnv[t], __shfl_down_sync(0xffffffffu, mnv[t], off));
            }
        }
    }
    const int wr_idx = wid >> 1;
    if (q == 0) {
#pragma unroll
        for (int t = 0; t < 8; t++) {
            int c = wc + (t >> 1) * 8 + 2 * s + (t & 1);
            Ps[wr_idx * 64 + c] = ps[t];
            Pq[wr_idx * 64 + c] = pq[t];
            if (REDUCE) {
                Mxs[wr_idx * 64 + c] = mxv[t];
                Mns[wr_idx * 64 + c] = mnv[t];
            }
        }
    }
    __syncthreads();

    if (tid < 64) {
        float sa = Ps[tid] + Ps[64 + tid] + Ps[128 + tid] + Ps[192 + tid];
        float qa = Pq[tid] + Pq[64 + tid] + Pq[128 + tid] + Pq[192 + tid];
        psum[(ob + tid) * NBLK + bx] = sa;
        psq [(ob + tid) * NBLK + bx] = qa;
    }
    if (REDUCE && tid < 128) {
        int half = tid >> 6, c = tid & 63;
        float mx = fmaxf(Mxs[(half * 2) * 64 + c], Mxs[(half * 2 + 1) * 64 + c]);
        float mn = fminf(Mns[(half * 2) * 64 + c], Mns[(half * 2 + 1) * 64 + c]);
        int node = bx * 2 + half;
        mxout[node * 128 + ob + c] = mx;
        mnout[node * 128 + ob + c] = mn;
    }
}

// ---------------------------------------------------------------------------
__global__ void __launch_bounds__(256) stats_finalize(
    const float* __restrict__ psum, const float* __restrict__ psq,
    const float* __restrict__ gamma, const float* __restrict__ beta,
    float* __restrict__ bna, float* __restrict__ bnc)
{
    const int o = blockIdx.x;
    const int tid = threadIdx.x;
    float s = 0.0f, q = 0.0f;
    for (int b = tid; b < NBLK; b += 256) {
        s += psum[o * NBLK + b];
        q += psq [o * NBLK + b];
    }
    __shared__ float sh[512];
    sh[tid] = s; sh[256 + tid] = q;
    __syncthreads();
    for (int st = 128; st > 0; st >>= 1) {
        if (tid < st) {
            sh[tid]       += sh[tid + st];
            sh[256 + tid] += sh[256 + tid + st];
        }
        __syncthreads();
    }
    if (tid == 0) {
        float mean = sh[0] / PCOUNT;
        float var  = sh[256] / PCOUNT - mean * mean;
        float a    = gamma[o] * rsqrtf(var + EPS);
        bna[o] = a;
        bnc[o] = beta[o] - mean * a;
    }
}

__global__ void __launch_bounds__(256) apply_out(
    const float* __restrict__ mx, const float* __restrict__ mn,
    const float* __restrict__ bna, const float* __restrict__ bnc,
    float* __restrict__ out)
{
    int idx = blockIdx.x * 256 + threadIdx.x;
    int c = idx & 127;
    float a = bna[c];
    float h = (a > 0.0f) ? mx[idx] : mn[idx];
    out[idx] = fmaxf(fmaf(a, h, bnc[c]), 0.0f);
}

// ---------------------------------------------------------------------------
extern "C" void kernel_launch(void* const* d_in, const int* in_sizes, int n_in,
                              void* d_out, int out_size)
{
    const float* x   = (const float*)d_in[0];
    const float* w0  = (const float*)d_in[1];
    const float* b0  = (const float*)d_in[2];
    const float* gm0 = (const float*)d_in[3];
    const float* be0 = (const float*)d_in[4];
    const float* w1  = (const float*)d_in[5];
    const float* b1  = (const float*)d_in[6];
    const float* gm1 = (const float*)d_in[7];
    const float* be1 = (const float*)d_in[8];
    const float* w2  = (const float*)d_in[9];
    const float* b2  = (const float*)d_in[10];
    const float* gm2 = (const float*)d_in[11];
    const float* be2 = (const float*)d_in[12];
    float* out = (float*)d_out;

    float *h0, *h1, *mx, *mn, *psum, *psq, *bna, *bnc;
    cudaGetSymbolAddress((void**)&h0,   g_h0);
    cudaGetSymbolAddress((void**)&h1,   g_h1);
    cudaGetSymbolAddress((void**)&mx,   g_mx);
    cudaGetSymbolAddress((void**)&mn,   g_mn);
    cudaGetSymbolAddress((void**)&psum, g_psum);
    cudaGetSymbolAddress((void**)&psq,  g_psq);
    cudaGetSymbolAddress((void**)&bna,  g_bna);
    cudaGetSymbolAddress((void**)&bnc,  g_bnc);

    cudaFuncSetAttribute(gemm_mma<67, false, false>,
                         cudaFuncAttributeMaxDynamicSharedMemorySize, SM_TOTAL);
    cudaFuncSetAttribute(gemm_mma<64, true, false>,
                         cudaFuncAttributeMaxDynamicSharedMemorySize, SM_TOTAL);
    cudaFuncSetAttribute(gemm_mma<64, true, true>,
                         cudaFuncAttributeMaxDynamicSharedMemorySize, SM_TOTAL);

    // L0: conv(67->64) + stats
    gemm_mma<67, false, false><<<dim3(NBLK, 1), 256, SM_TOTAL>>>(
        x, w0, b0, nullptr, nullptr, h0, nullptr, nullptr, psum, psq);
    stats_finalize<<<64, 256>>>(psum, psq, gm0, be0, bna, bnc);

    // L1: bn0+relu on load -> conv(64->64) + stats
    gemm_mma<64, true, false><<<dim3(NBLK, 1), 256, SM_TOTAL>>>(
        h0, w1, b1, bna, bnc, h1, nullptr, nullptr, psum, psq);
    stats_finalize<<<64, 256>>>(psum, psq, gm1, be1, bna, bnc);

    // L2: bn1+relu on load -> conv(64->128 in two N-halves) + stats
    //     + fused per-node max/min (no H2 materialization)
    gemm_mma<64, true, true><<<dim3(NBLK, 2), 256, SM_TOTAL>>>(
        h1, w2, b2, bna, bnc, nullptr, mx, mn, psum, psq);
    stats_finalize<<<128, 256>>>(psum, psq, gm2, be2, bna, bnc);

    apply_out<<<(NNODES * 128) / 256, 256>>>(mx, mn, bna, bnc, out);
}

// round 8
// speedup vs baseline: 2.5375x; 1.8799x over previous
#include <cuda_runtime.h>
#include <cuda_bf16.h>
#include <math_constants.h>
#include <cstdint>

// ---------------------------------------------------------------------------
// PointNetConv via mma.sync bf16 m16n8k16, 3-term split (~1e-5 accuracy)
//   3x (1x1 conv -> BN(train) -> ReLU) -> max over K=64 neighbors
// Round-7: register-batched LDG prefetch in convert phase (MLP=16),
// BN params loaded per-thread from global (drops a barrier + smem stage),
// dummy first launch so ncu (-s 5 -c 1) captures the L2 GEMM kernel.
// ---------------------------------------------------------------------------

#define TOTAL_ROWS (16384 * 64)
#define NBLK       8192
#define NNODES     16384
#define EPS        1e-5f
#define PCOUNT     ((float)TOTAL_ROWS)

__device__ float g_h0[TOTAL_ROWS * 64];
__device__ float g_h1[TOTAL_ROWS * 64];
__device__ float g_mx[NNODES * 128];
__device__ float g_mn[NNODES * 128];
__device__ float g_psum[128 * NBLK];
__device__ float g_psq [128 * NBLK];
__device__ float g_bna[128];
__device__ float g_bnc[128];

// ---- smem byte offsets ----
#define SM_BIAS   0
#define SM_WE     768
#define SM_XE     1792
#define SM_PS     3840
#define SM_PQ     4864
#define SM_MX     5888
#define SM_MN     6912
#define SM_A      8192                    // 128*34 uint2 = 34816 B
#define SM_B      (8192 + 34816)          // 64*36 uint2  = 18432 B
#define SM_TOTAL  (8192 + 34816 + 18432)  // 61440 B -> 3 CTAs/SM

#define AS 34   // A pair-stride (uint2)
#define BS 36   // B pair-stride (uint2)

// split two fp32 (k-even, k-odd) into packed bf16x2 hi and lo words
static __device__ __forceinline__ uint2 split2_bf16(float v0, float v1) {
    __nv_bfloat16 h0 = __float2bfloat16_rn(v0);
    __nv_bfloat16 h1 = __float2bfloat16_rn(v1);
    float r0 = v0 - __bfloat162float(h0);
    float r1 = v1 - __bfloat162float(h1);
    __nv_bfloat16 l0 = __float2bfloat16_rn(r0);
    __nv_bfloat16 l1 = __float2bfloat16_rn(r1);
    uint32_t hi = (uint32_t)__bfloat16_as_ushort(h0) |
                  ((uint32_t)__bfloat16_as_ushort(h1) << 16);
    uint32_t lo = (uint32_t)__bfloat16_as_ushort(l0) |
                  ((uint32_t)__bfloat16_as_ushort(l1) << 16);
    return make_uint2(hi, lo);
}

static __device__ __forceinline__ void mma_bf16(float* c, const uint32_t* a,
                                                const uint32_t* b) {
    asm volatile(
        "mma.sync.aligned.m16n8k16.row.col.f32.bf16.bf16.f32 "
        "{%0,%1,%2,%3}, {%4,%5,%6,%7}, {%8,%9}, {%0,%1,%2,%3};"
        : "+f"(c[0]), "+f"(c[1]), "+f"(c[2]), "+f"(c[3])
        : "r"(a[0]), "r"(a[1]), "r"(a[2]), "r"(a[3]), "r"(b[0]), "r"(b[1]));
}

__global__ void warmup_dummy() {}   // shifts ncu capture window onto a GEMM

// ---------------------------------------------------------------------------
template <int CIN, bool BN_IN, bool REDUCE>
__global__ void __launch_bounds__(256, 3) gemm_mma(
    const float* __restrict__ X, const float* __restrict__ W,
    const float* __restrict__ B,
    const float* __restrict__ bna, const float* __restrict__ bnc,
    float* __restrict__ H, float* __restrict__ mxout, float* __restrict__ mnout,
    float* __restrict__ psum, float* __restrict__ psq)
{
    extern __shared__ char smem[];
    float* Bsm = (float*)(smem + SM_BIAS);
    float* We  = (float*)(smem + SM_WE);
    float* Xe  = (float*)(smem + SM_XE);
    float* Ps  = (float*)(smem + SM_PS);
    float* Pq  = (float*)(smem + SM_PQ);
    float* Mxs = (float*)(smem + SM_MX);
    float* Mns = (float*)(smem + SM_MN);
    uint2* Ap  = (uint2*)(smem + SM_A);   // [128][AS] (hiPair, loPair)
    uint2* Bp  = (uint2*)(smem + SM_B);   // [64][BS]

    const int tid  = threadIdx.x;
    const int wid  = tid >> 5;
    const int lane = tid & 31;
    const int q = lane >> 2, s = lane & 3;
    const int bx = blockIdx.x;
    const int ob = blockIdx.y * 64;
    const long long row0 = (long long)bx * 128;
    const int rg = tid >> 5;          // row/col group for convert loops
    const int l2 = 2 * lane;          // fixed channel pair per thread

    if (tid < 64) Bsm[tid] = B[ob + tid];

    // BN affine for this thread's fixed channel pair (no smem, no barrier)
    float ba0 = 0.f, ba1 = 0.f, bc0 = 0.f, bc1 = 0.f;
    if (BN_IN) {
        float2 t = *(const float2*)&bna[l2];
        float2 u = *(const float2*)&bnc[l2];
        ba0 = t.x; ba1 = t.y; bc0 = u.x; bc1 = u.y;
    }

    // ---- W -> Bp pairs: batch-prefetch 8 rows (n = rg + 8i, pr = lane) ----
    {
        float wv0[8], wv1[8];
#pragma unroll
        for (int i = 0; i < 8; i++) {
            int n = rg + 8 * i;
            if (CIN == 64) {
                float2 v = *(const float2*)&W[(ob + n) * 64 + l2];
                wv0[i] = v.x; wv1[i] = v.y;
            } else {
                wv0[i] = W[(ob + n) * CIN + l2];
                wv1[i] = W[(ob + n) * CIN + l2 + 1];
            }
        }
#pragma unroll
        for (int i = 0; i < 8; i++)
            Bp[(rg + 8 * i) * BS + lane] = split2_bf16(wv0[i], wv1[i]);
    }

    // ---- X -> Ap pairs: batch-prefetch 16 rows (r = rg + 8i, pr = lane) ----
    {
        float xv0[16], xv1[16];
#pragma unroll
        for (int i = 0; i < 16; i++) {
            int r = rg + 8 * i;
            if (CIN == 64) {
                float2 v = *(const float2*)&X[(row0 + r) * 64 + l2];
                xv0[i] = v.x; xv1[i] = v.y;
            } else {
                xv0[i] = X[(row0 + r) * CIN + l2];
                xv1[i] = X[(row0 + r) * CIN + l2 + 1];
            }
        }
#pragma unroll
        for (int i = 0; i < 16; i++) {
            float v0 = xv0[i], v1 = xv1[i];
            if (BN_IN) {
                v0 = fmaxf(fmaf(ba0, v0, bc0), 0.0f);
                v1 = fmaxf(fmaf(ba1, v1, bc1), 0.0f);
            }
            Ap[(rg + 8 * i) * AS + lane] = split2_bf16(v0, v1);
        }
    }
    if (CIN == 67) {
        for (int p = tid; p < 64 * 4; p += 256) {
            int o = p >> 2, j = p & 3;
            We[p] = (j < 3) ? W[(ob + o) * 67 + 64 + j] : 0.0f;
        }
        for (int p = tid; p < 128 * 4; p += 256) {
            int r = p >> 2, j = p & 3;
            Xe[p] = (j < 3) ? X[(row0 + r) * 67 + 64 + j] : 0.0f;
        }
    }
    __syncthreads();

    // ---- MMA mainloop: warp tile 32x32, K=64 in 4 k16-steps ----
    const int wr = (wid >> 1) * 32;
    const int wc = (wid & 1) * 32;

    float acc[8][4];
#pragma unroll
    for (int t = 0; t < 8; t++)
#pragma unroll
        for (int j = 0; j < 4; j++) acc[t][j] = 0.0f;

#pragma unroll
    for (int kk = 0; kk < 4; kk++) {
        const int pb = kk * 8 + s;
        uint32_t ah[2][4], al[2][4];
#pragma unroll
        for (int mt = 0; mt < 2; mt++) {
            int r0 = wr + mt * 16 + q;
            uint2 a0 = Ap[(r0    ) * AS + pb];      // k=2s,2s+1
            uint2 a1 = Ap[(r0 + 8) * AS + pb];
            uint2 a2 = Ap[(r0    ) * AS + pb + 4];  // k=2s+8,2s+9
            uint2 a3 = Ap[(r0 + 8) * AS + pb + 4];
            ah[mt][0] = a0.x; al[mt][0] = a0.y;
            ah[mt][1] = a1.x; al[mt][1] = a1.y;
            ah[mt][2] = a2.x; al[mt][2] = a2.y;
            ah[mt][3] = a3.x; al[mt][3] = a3.y;
        }
#pragma unroll
        for (int nt = 0; nt < 4; nt++) {
            int n = wc + nt * 8 + q;
            uint2 b0 = Bp[n * BS + pb];
            uint2 b1 = Bp[n * BS + pb + 4];
            uint32_t bh[2] = {b0.x, b1.x};
            uint32_t bl[2] = {b0.y, b1.y};
#pragma unroll
            for (int mt = 0; mt < 2; mt++) {
                mma_bf16(acc[mt * 4 + nt], ah[mt], bh);
                mma_bf16(acc[mt * 4 + nt], al[mt], bh);
                mma_bf16(acc[mt * 4 + nt], ah[mt], bl);
            }
        }
    }

    // ---- epilogue: bias (+L0 exact extra channels), stats, max/min ----
    float ps[8], pq[8], mxv[8], mnv[8];
#pragma unroll
    for (int t = 0; t < 8; t++) {
        ps[t] = 0.0f; pq[t] = 0.0f;
        mxv[t] = -CUDART_INF_F; mnv[t] = CUDART_INF_F;
    }

#pragma unroll
    for (int mt = 0; mt < 2; mt++) {
#pragma unroll
        for (int h = 0; h < 2; h++) {
            int r = wr + mt * 16 + q + h * 8;
            float4 xe = make_float4(0.f, 0.f, 0.f, 0.f);
            if (CIN == 67) xe = *(float4*)&Xe[r * 4];
#pragma unroll
            for (int nt = 0; nt < 4; nt++) {
                int cb = wc + nt * 8 + 2 * s;
                float v0 = acc[mt * 4 + nt][h * 2 + 0] + Bsm[cb];
                float v1 = acc[mt * 4 + nt][h * 2 + 1] + Bsm[cb + 1];
                if (CIN == 67) {
                    float4 w0 = *(float4*)&We[cb * 4];
                    float4 w1 = *(float4*)&We[(cb + 1) * 4];
                    v0 += w0.x * xe.x + w0.y * xe.y + w0.z * xe.z;
                    v1 += w1.x * xe.x + w1.y * xe.y + w1.z * xe.z;
                }
                if (!REDUCE)
                    *(float2*)&H[(row0 + r) * 64 + cb] = make_float2(v0, v1);
                int t0 = nt * 2, t1 = nt * 2 + 1;
                ps[t0] += v0; pq[t0] += v0 * v0;
                ps[t1] += v1; pq[t1] += v1 * v1;
                if (REDUCE) {
                    mxv[t0] = fmaxf(mxv[t0], v0); mnv[t0] = fminf(mnv[t0], v0);
                    mxv[t1] = fmaxf(mxv[t1], v1); mnv[t1] = fminf(mnv[t1], v1);
                }
            }
        }
    }

    // warp reduce over q (offsets 16, 8, 4)
#pragma unroll
    for (int off = 16; off >= 4; off >>= 1) {
#pragma unroll
        for (int t = 0; t < 8; t++) {
            ps[t] += __shfl_down_sync(0xffffffffu, ps[t], off);
            pq[t] += __shfl_down_sync(0xffffffffu, pq[t], off);
            if (REDUCE) {
                mxv[t] = fmaxf(mxv[t], __shfl_down_sync(0xffffffffu, mxv[t], off));
                mnv[t] = fminf(mnv[t], __shfl_down_sync(0xffffffffu, mnv[t], off));
            }
        }
    }
    const int wr_idx = wid >> 1;
    if (q == 0) {
#pragma unroll
        for (int t = 0; t < 8; t++) {
            int c = wc + (t >> 1) * 8 + 2 * s + (t & 1);
            Ps[wr_idx * 64 + c] = ps[t];
            Pq[wr_idx * 64 + c] = pq[t];
            if (REDUCE) {
                Mxs[wr_idx * 64 + c] = mxv[t];
                Mns[wr_idx * 64 + c] = mnv[t];
            }
        }
    }
    __syncthreads();

    if (tid < 64) {
        float sa = Ps[tid] + Ps[64 + tid] + Ps[128 + tid] + Ps[192 + tid];
        float qa = Pq[tid] + Pq[64 + tid] + Pq[128 + tid] + Pq[192 + tid];
        psum[(ob + tid) * NBLK + bx] = sa;
        psq [(ob + tid) * NBLK + bx] = qa;
    }
    if (REDUCE && tid < 128) {
        int half = tid >> 6, c = tid & 63;
        float mx = fmaxf(Mxs[(half * 2) * 64 + c], Mxs[(half * 2 + 1) * 64 + c]);
        float mn = fminf(Mns[(half * 2) * 64 + c], Mns[(half * 2 + 1) * 64 + c]);
        int node = bx * 2 + half;
        mxout[node * 128 + ob + c] = mx;
        mnout[node * 128 + ob + c] = mn;
    }
}

// ---------------------------------------------------------------------------
__global__ void __launch_bounds__(256) stats_finalize(
    const float* __restrict__ psum, const float* __restrict__ psq,
    const float* __restrict__ gamma, const float* __restrict__ beta,
    float* __restrict__ bna, float* __restrict__ bnc)
{
    const int o = blockIdx.x;
    const int tid = threadIdx.x;
    float s = 0.0f, q = 0.0f;
    for (int b = tid; b < NBLK; b += 256) {
        s += psum[o * NBLK + b];
        q += psq [o * NBLK + b];
    }
    __shared__ float sh[512];
    sh[tid] = s; sh[256 + tid] = q;
    __syncthreads();
    for (int st = 128; st > 0; st >>= 1) {
        if (tid < st) {
            sh[tid]       += sh[tid + st];
            sh[256 + tid] += sh[256 + tid + st];
        }
        __syncthreads();
    }
    if (tid == 0) {
        float mean = sh[0] / PCOUNT;
        float var  = sh[256] / PCOUNT - mean * mean;
        float a    = gamma[o] * rsqrtf(var + EPS);
        bna[o] = a;
        bnc[o] = beta[o] - mean * a;
    }
}

__global__ void __launch_bounds__(256) apply_out(
    const float* __restrict__ mx, const float* __restrict__ mn,
    const float* __restrict__ bna, const float* __restrict__ bnc,
    float* __restrict__ out)
{
    int idx = blockIdx.x * 256 + threadIdx.x;
    int c = idx & 127;
    float a = bna[c];
    float h = (a > 0.0f) ? mx[idx] : mn[idx];
    out[idx] = fmaxf(fmaf(a, h, bnc[c]), 0.0f);
}

// ---------------------------------------------------------------------------
extern "C" void kernel_launch(void* const* d_in, const int* in_sizes, int n_in,
                              void* d_out, int out_size)
{
    const float* x   = (const float*)d_in[0];
    const float* w0  = (const float*)d_in[1];
    const float* b0  = (const float*)d_in[2];
    const float* gm0 = (const float*)d_in[3];
    const float* be0 = (const float*)d_in[4];
    const float* w1  = (const float*)d_in[5];
    const float* b1  = (const float*)d_in[6];
    const float* gm1 = (const float*)d_in[7];
    const float* be1 = (const float*)d_in[8];
    const float* w2  = (const float*)d_in[9];
    const float* b2  = (const float*)d_in[10];
    const float* gm2 = (const float*)d_in[11];
    const float* be2 = (const float*)d_in[12];
    float* out = (float*)d_out;

    float *h0, *h1, *mx, *mn, *psum, *psq, *bna, *bnc;
    cudaGetSymbolAddress((void**)&h0,   g_h0);
    cudaGetSymbolAddress((void**)&h1,   g_h1);
    cudaGetSymbolAddress((void**)&mx,   g_mx);
    cudaGetSymbolAddress((void**)&mn,   g_mn);
    cudaGetSymbolAddress((void**)&psum, g_psum);
    cudaGetSymbolAddress((void**)&psq,  g_psq);
    cudaGetSymbolAddress((void**)&bna,  g_bna);
    cudaGetSymbolAddress((void**)&bnc,  g_bnc);

    cudaFuncSetAttribute(gemm_mma<67, false, false>,
                         cudaFuncAttributeMaxDynamicSharedMemorySize, SM_TOTAL);
    cudaFuncSetAttribute(gemm_mma<64, true, false>,
                         cudaFuncAttributeMaxDynamicSharedMemorySize, SM_TOTAL);
    cudaFuncSetAttribute(gemm_mma<64, true, true>,
                         cudaFuncAttributeMaxDynamicSharedMemorySize, SM_TOTAL);

    warmup_dummy<<<1, 32>>>();   // launch #1: shifts ncu (-s 5) onto L2 GEMM

    // L0: conv(67->64) + stats
    gemm_mma<67, false, false><<<dim3(NBLK, 1), 256, SM_TOTAL>>>(
        x, w0, b0, nullptr, nullptr, h0, nullptr, nullptr, psum, psq);
    stats_finalize<<<64, 256>>>(psum, psq, gm0, be0, bna, bnc);

    // L1: bn0+relu on load -> conv(64->64) + stats
    gemm_mma<64, true, false><<<dim3(NBLK, 1), 256, SM_TOTAL>>>(
        h0, w1, b1, bna, bnc, h1, nullptr, nullptr, psum, psq);
    stats_finalize<<<64, 256>>>(psum, psq, gm1, be1, bna, bnc);

    // L2: bn1+relu on load -> conv(64->128 in two N-halves) + stats
    //     + fused per-node max/min (no H2 materialization)  [ncu launch #6]
    gemm_mma<64, true, true><<<dim3(NBLK, 2), 256, SM_TOTAL>>>(
        h1, w2, b2, bna, bnc, nullptr, mx, mn, psum, psq);
    stats_finalize<<<128, 256>>>(psum, psq, gm2, be2, bna, bnc);

    apply_out<<<(NNODES * 128) / 256, 256>>>(mx, mn, bna, bnc, out);
}

// round 9
// speedup vs baseline: 2.5728x; 1.0139x over previous
#include <cuda_runtime.h>
#include <cuda_bf16.h>
#include <math_constants.h>
#include <cstdint>

// ---------------------------------------------------------------------------
// PointNetConv via mma.sync bf16 m16n8k16, 3-term split (~1e-5 accuracy)
//   3x (1x1 conv -> BN(train) -> ReLU) -> max over K=64 neighbors
// Round-9: A pair-stride 34 -> 36 (kills 2-way LDS bank conflict in the
// mainloop: 36 ≡ 4 mod 16 makes phase bank-pairs 4q+s a bijection), and
// L2 grid swapped to (2, NBLK) so the two N-half CTAs sharing an h1 tile are
// launch-adjacent -> second h1 read hits L2 instead of DRAM (-268 MB).
// ---------------------------------------------------------------------------

#define TOTAL_ROWS (16384 * 64)
#define NBLK       8192
#define NNODES     16384
#define EPS        1e-5f
#define PCOUNT     ((float)TOTAL_ROWS)

__device__ float g_h0[TOTAL_ROWS * 64];
__device__ float g_h1[TOTAL_ROWS * 64];
__device__ float g_mx[NNODES * 128];
__device__ float g_mn[NNODES * 128];
__device__ float g_psum[128 * NBLK];
__device__ float g_psq [128 * NBLK];
__device__ float g_bna[128];
__device__ float g_bnc[128];

// ---- smem byte offsets ----
#define SM_BIAS   0
#define SM_WE     768
#define SM_XE     1792
#define SM_PS     3840
#define SM_PQ     4864
#define SM_MX     5888
#define SM_MN     6912
#define SM_A      8192                    // 128*36 uint2 = 36864 B
#define SM_B      (8192 + 36864)          // 64*36 uint2  = 18432 B
#define SM_TOTAL  (8192 + 36864 + 18432)  // 63488 B -> 3 CTAs/SM

#define AS 36   // A pair-stride (uint2): 36 mod 16 = 4 -> conflict-free frags
#define BS 36   // B pair-stride (uint2)

// split two fp32 (k-even, k-odd) into packed bf16x2 hi and lo words
static __device__ __forceinline__ uint2 split2_bf16(float v0, float v1) {
    __nv_bfloat16 h0 = __float2bfloat16_rn(v0);
    __nv_bfloat16 h1 = __float2bfloat16_rn(v1);
    float r0 = v0 - __bfloat162float(h0);
    float r1 = v1 - __bfloat162float(h1);
    __nv_bfloat16 l0 = __float2bfloat16_rn(r0);
    __nv_bfloat16 l1 = __float2bfloat16_rn(r1);
    uint32_t hi = (uint32_t)__bfloat16_as_ushort(h0) |
                  ((uint32_t)__bfloat16_as_ushort(h1) << 16);
    uint32_t lo = (uint32_t)__bfloat16_as_ushort(l0) |
                  ((uint32_t)__bfloat16_as_ushort(l1) << 16);
    return make_uint2(hi, lo);
}

static __device__ __forceinline__ void mma_bf16(float* c, const uint32_t* a,
                                                const uint32_t* b) {
    asm volatile(
        "mma.sync.aligned.m16n8k16.row.col.f32.bf16.bf16.f32 "
        "{%0,%1,%2,%3}, {%4,%5,%6,%7}, {%8,%9}, {%0,%1,%2,%3};"
        : "+f"(c[0]), "+f"(c[1]), "+f"(c[2]), "+f"(c[3])
        : "r"(a[0]), "r"(a[1]), "r"(a[2]), "r"(a[3]), "r"(b[0]), "r"(b[1]));
}

__global__ void warmup_dummy() {}   // shifts ncu capture window onto a GEMM

// ---------------------------------------------------------------------------
template <int CIN, bool BN_IN, bool REDUCE>
__global__ void __launch_bounds__(256, 3) gemm_mma(
    const float* __restrict__ X, const float* __restrict__ W,
    const float* __restrict__ B,
    const float* __restrict__ bna, const float* __restrict__ bnc,
    float* __restrict__ H, float* __restrict__ mxout, float* __restrict__ mnout,
    float* __restrict__ psum, float* __restrict__ psq)
{
    extern __shared__ char smem[];
    float* Bsm = (float*)(smem + SM_BIAS);
    float* We  = (float*)(smem + SM_WE);
    float* Xe  = (float*)(smem + SM_XE);
    float* Ps  = (float*)(smem + SM_PS);
    float* Pq  = (float*)(smem + SM_PQ);
    float* Mxs = (float*)(smem + SM_MX);
    float* Mns = (float*)(smem + SM_MN);
    uint2* Ap  = (uint2*)(smem + SM_A);   // [128][AS] (hiPair, loPair)
    uint2* Bp  = (uint2*)(smem + SM_B);   // [64][BS]

    const int tid  = threadIdx.x;
    const int wid  = tid >> 5;
    const int lane = tid & 31;
    const int q = lane >> 2, s = lane & 3;
    // REDUCE: grid (2, NBLK) -> N-half fastest so both halves of a row tile
    // are launch-adjacent (h1 tile hits L2 on the second read).
    const int bx = REDUCE ? blockIdx.y : blockIdx.x;
    const int ob = (REDUCE ? blockIdx.x : blockIdx.y) * 64;
    const long long row0 = (long long)bx * 128;
    const int rg = tid >> 5;          // row/col group for convert loops
    const int l2 = 2 * lane;          // fixed channel pair per thread

    if (tid < 64) Bsm[tid] = B[ob + tid];

    // BN affine for this thread's fixed channel pair (no smem, no barrier)
    float ba0 = 0.f, ba1 = 0.f, bc0 = 0.f, bc1 = 0.f;
    if (BN_IN) {
        float2 t = *(const float2*)&bna[l2];
        float2 u = *(const float2*)&bnc[l2];
        ba0 = t.x; ba1 = t.y; bc0 = u.x; bc1 = u.y;
    }

    // ---- W -> Bp pairs: batch-prefetch 8 rows (n = rg + 8i, pr = lane) ----
    {
        float wv0[8], wv1[8];
#pragma unroll
        for (int i = 0; i < 8; i++) {
            int n = rg + 8 * i;
            if (CIN == 64) {
                float2 v = *(const float2*)&W[(ob + n) * 64 + l2];
                wv0[i] = v.x; wv1[i] = v.y;
            } else {
                wv0[i] = W[(ob + n) * CIN + l2];
                wv1[i] = W[(ob + n) * CIN + l2 + 1];
            }
        }
#pragma unroll
        for (int i = 0; i < 8; i++)
            Bp[(rg + 8 * i) * BS + lane] = split2_bf16(wv0[i], wv1[i]);
    }

    // ---- X -> Ap pairs: batch-prefetch 16 rows (r = rg + 8i, pr = lane) ----
    {
        float xv0[16], xv1[16];
#pragma unroll
        for (int i = 0; i < 16; i++) {
            int r = rg + 8 * i;
            if (CIN == 64) {
                float2 v = *(const float2*)&X[(row0 + r) * 64 + l2];
                xv0[i] = v.x; xv1[i] = v.y;
            } else {
                xv0[i] = X[(row0 + r) * CIN + l2];
                xv1[i] = X[(row0 + r) * CIN + l2 + 1];
            }
        }
#pragma unroll
        for (int i = 0; i < 16; i++) {
            float v0 = xv0[i], v1 = xv1[i];
            if (BN_IN) {
                v0 = fmaxf(fmaf(ba0, v0, bc0), 0.0f);
                v1 = fmaxf(fmaf(ba1, v1, bc1), 0.0f);
            }
            Ap[(rg + 8 * i) * AS + lane] = split2_bf16(v0, v1);
        }
    }
    if (CIN == 67) {
        for (int p = tid; p < 64 * 4; p += 256) {
            int o = p >> 2, j = p & 3;
            We[p] = (j < 3) ? W[(ob + o) * 67 + 64 + j] : 0.0f;
        }
        for (int p = tid; p < 128 * 4; p += 256) {
            int r = p >> 2, j = p & 3;
            Xe[p] = (j < 3) ? X[(row0 + r) * 67 + 64 + j] : 0.0f;
        }
    }
    __syncthreads();

    // ---- MMA mainloop: warp tile 32x32, K=64 in 4 k16-steps ----
    const int wr = (wid >> 1) * 32;
    const int wc = (wid & 1) * 32;

    float acc[8][4];
#pragma unroll
    for (int t = 0; t < 8; t++)
#pragma unroll
        for (int j = 0; j < 4; j++) acc[t][j] = 0.0f;

#pragma unroll
    for (int kk = 0; kk < 4; kk++) {
        const int pb = kk * 8 + s;
        uint32_t ah[2][4], al[2][4];
#pragma unroll
        for (int mt = 0; mt < 2; mt++) {
            int r0 = wr + mt * 16 + q;
            uint2 a0 = Ap[(r0    ) * AS + pb];      // k=2s,2s+1
            uint2 a1 = Ap[(r0 + 8) * AS + pb];
            uint2 a2 = Ap[(r0    ) * AS + pb + 4];  // k=2s+8,2s+9
            uint2 a3 = Ap[(r0 + 8) * AS + pb + 4];
            ah[mt][0] = a0.x; al[mt][0] = a0.y;
            ah[mt][1] = a1.x; al[mt][1] = a1.y;
            ah[mt][2] = a2.x; al[mt][2] = a2.y;
            ah[mt][3] = a3.x; al[mt][3] = a3.y;
        }
#pragma unroll
        for (int nt = 0; nt < 4; nt++) {
            int n = wc + nt * 8 + q;
            uint2 b0 = Bp[n * BS + pb];
            uint2 b1 = Bp[n * BS + pb + 4];
            uint32_t bh[2] = {b0.x, b1.x};
            uint32_t bl[2] = {b0.y, b1.y};
#pragma unroll
            for (int mt = 0; mt < 2; mt++) {
                mma_bf16(acc[mt * 4 + nt], ah[mt], bh);
                mma_bf16(acc[mt * 4 + nt], al[mt], bh);
                mma_bf16(acc[mt * 4 + nt], ah[mt], bl);
            }
        }
    }

    // ---- epilogue: bias (+L0 exact extra channels), stats, max/min ----
    float ps[8], pq[8], mxv[8], mnv[8];
#pragma unroll
    for (int t = 0; t < 8; t++) {
        ps[t] = 0.0f; pq[t] = 0.0f;
        mxv[t] = -CUDART_INF_F; mnv[t] = CUDART_INF_F;
    }

#pragma unroll
    for (int mt = 0; mt < 2; mt++) {
#pragma unroll
        for (int h = 0; h < 2; h++) {
            int r = wr + mt * 16 + q + h * 8;
            float4 xe = make_float4(0.f, 0.f, 0.f, 0.f);
            if (CIN == 67) xe = *(float4*)&Xe[r * 4];
#pragma unroll
            for (int nt = 0; nt < 4; nt++) {
                int cb = wc + nt * 8 + 2 * s;
                float v0 = acc[mt * 4 + nt][h * 2 + 0] + Bsm[cb];
                float v1 = acc[mt * 4 + nt][h * 2 + 1] + Bsm[cb + 1];
                if (CIN == 67) {
                    float4 w0 = *(float4*)&We[cb * 4];
                    float4 w1 = *(float4*)&We[(cb + 1) * 4];
                    v0 += w0.x * xe.x + w0.y * xe.y + w0.z * xe.z;
                    v1 += w1.x * xe.x + w1.y * xe.y + w1.z * xe.z;
                }
                if (!REDUCE)
                    *(float2*)&H[(row0 + r) * 64 + cb] = make_float2(v0, v1);
                int t0 = nt * 2, t1 = nt * 2 + 1;
                ps[t0] += v0; pq[t0] += v0 * v0;
                ps[t1] += v1; pq[t1] += v1 * v1;
                if (REDUCE) {
                    mxv[t0] = fmaxf(mxv[t0], v0); mnv[t0] = fminf(mnv[t0], v0);
                    mxv[t1] = fmaxf(mxv[t1], v1); mnv[t1] = fminf(mnv[t1], v1);
                }
            }
        }
    }

    // warp reduce over q (offsets 16, 8, 4)
#pragma unroll
    for (int off = 16; off >= 4; off >>= 1) {
#pragma unroll
        for (int t = 0; t < 8; t++) {
            ps[t] += __shfl_down_sync(0xffffffffu, ps[t], off);
            pq[t] += __shfl_down_sync(0xffffffffu, pq[t], off);
            if (REDUCE) {
                mxv[t] = fmaxf(mxv[t], __shfl_down_sync(0xffffffffu, mxv[t], off));
                mnv[t] = fminf(mnv[t], __shfl_down_sync(0xffffffffu, mnv[t], off));
            }
        }
    }
    const int wr_idx = wid >> 1;
    if (q == 0) {
#pragma unroll
        for (int t = 0; t < 8; t++) {
            int c = wc + (t >> 1) * 8 + 2 * s + (t & 1);
            Ps[wr_idx * 64 + c] = ps[t];
            Pq[wr_idx * 64 + c] = pq[t];
            if (REDUCE) {
                Mxs[wr_idx * 64 + c] = mxv[t];
                Mns[wr_idx * 64 + c] = mnv[t];
            }
        }
    }
    __syncthreads();

    if (tid < 64) {
        float sa = Ps[tid] + Ps[64 + tid] + Ps[128 + tid] + Ps[192 + tid];
        float qa = Pq[tid] + Pq[64 + tid] + Pq[128 + tid] + Pq[192 + tid];
        psum[(ob + tid) * NBLK + bx] = sa;
        psq [(ob + tid) * NBLK + bx] = qa;
    }
    if (REDUCE && tid < 128) {
        int half = tid >> 6, c = tid & 63;
        float mx = fmaxf(Mxs[(half * 2) * 64 + c], Mxs[(half * 2 + 1) * 64 + c]);
        float mn = fminf(Mns[(half * 2) * 64 + c], Mns[(half * 2 + 1) * 64 + c]);
        int node = bx * 2 + half;
        mxout[node * 128 + ob + c] = mx;
        mnout[node * 128 + ob + c] = mn;
    }
}

// ---------------------------------------------------------------------------
__global__ void __launch_bounds__(256) stats_finalize(
    const float* __restrict__ psum, const float* __restrict__ psq,
    const float* __restrict__ gamma, const float* __restrict__ beta,
    float* __restrict__ bna, float* __restrict__ bnc)
{
    const int o = blockIdx.x;
    const int tid = threadIdx.x;
    float s = 0.0f, q = 0.0f;
    for (int b = tid; b < NBLK; b += 256) {
        s += psum[o * NBLK + b];
        q += psq [o * NBLK + b];
    }
    __shared__ float sh[512];
    sh[tid] = s; sh[256 + tid] = q;
    __syncthreads();
    for (int st = 128; st > 0; st >>= 1) {
        if (tid < st) {
            sh[tid]       += sh[tid + st];
            sh[256 + tid] += sh[256 + tid + st];
        }
        __syncthreads();
    }
    if (tid == 0) {
        float mean = sh[0] / PCOUNT;
        float var  = sh[256] / PCOUNT - mean * mean;
        float a    = gamma[o] * rsqrtf(var + EPS);
        bna[o] = a;
        bnc[o] = beta[o] - mean * a;
    }
}

__global__ void __launch_bounds__(256) apply_out(
    const float* __restrict__ mx, const float* __restrict__ mn,
    const float* __restrict__ bna, const float* __restrict__ bnc,
    float* __restrict__ out)
{
    int idx = blockIdx.x * 256 + threadIdx.x;
    int c = idx & 127;
    float a = bna[c];
    float h = (a > 0.0f) ? mx[idx] : mn[idx];
    out[idx] = fmaxf(fmaf(a, h, bnc[c]), 0.0f);
}

// ---------------------------------------------------------------------------
extern "C" void kernel_launch(void* const* d_in, const int* in_sizes, int n_in,
                              void* d_out, int out_size)
{
    const float* x   = (const float*)d_in[0];
    const float* w0  = (const float*)d_in[1];
    const float* b0  = (const float*)d_in[2];
    const float* gm0 = (const float*)d_in[3];
    const float* be0 = (const float*)d_in[4];
    const float* w1  = (const float*)d_in[5];
    const float* b1  = (const float*)d_in[6];
    const float* gm1 = (const float*)d_in[7];
    const float* be1 = (const float*)d_in[8];
    const float* w2  = (const float*)d_in[9];
    const float* b2  = (const float*)d_in[10];
    const float* gm2 = (const float*)d_in[11];
    const float* be2 = (const float*)d_in[12];
    float* out = (float*)d_out;

    float *h0, *h1, *mx, *mn, *psum, *psq, *bna, *bnc;
    cudaGetSymbolAddress((void**)&h0,   g_h0);
    cudaGetSymbolAddress((void**)&h1,   g_h1);
    cudaGetSymbolAddress((void**)&mx,   g_mx);
    cudaGetSymbolAddress((void**)&mn,   g_mn);
    cudaGetSymbolAddress((void**)&psum, g_psum);
    cudaGetSymbolAddress((void**)&psq,  g_psq);
    cudaGetSymbolAddress((void**)&bna,  g_bna);
    cudaGetSymbolAddress((void**)&bnc,  g_bnc);

    cudaFuncSetAttribute(gemm_mma<67, false, false>,
                         cudaFuncAttributeMaxDynamicSharedMemorySize, SM_TOTAL);
    cudaFuncSetAttribute(gemm_mma<64, true, false>,
                         cudaFuncAttributeMaxDynamicSharedMemorySize, SM_TOTAL);
    cudaFuncSetAttribute(gemm_mma<64, true, true>,
                         cudaFuncAttributeMaxDynamicSharedMemorySize, SM_TOTAL);

    warmup_dummy<<<1, 32>>>();   // launch #1: shifts ncu (-s 5) onto L2 GEMM

    // L0: conv(67->64) + stats
    gemm_mma<67, false, false><<<dim3(NBLK, 1), 256, SM_TOTAL>>>(
        x, w0, b0, nullptr, nullptr, h0, nullptr, nullptr, psum, psq);
    stats_finalize<<<64, 256>>>(psum, psq, gm0, be0, bna, bnc);

    // L1: bn0+relu on load -> conv(64->64) + stats
    gemm_mma<64, true, false><<<dim3(NBLK, 1), 256, SM_TOTAL>>>(
        h0, w1, b1, bna, bnc, h1, nullptr, nullptr, psum, psq);
    stats_finalize<<<64, 256>>>(psum, psq, gm1, be1, bna, bnc);

    // L2: bn1+relu on load -> conv(64->128, grid (2, NBLK): halves adjacent
    //     so the second h1 tile read hits L2) + stats + per-node max/min
    gemm_mma<64, true, true><<<dim3(2, NBLK), 256, SM_TOTAL>>>(
        h1, w2, b2, bna, bnc, nullptr, mx, mn, psum, psq);
    stats_finalize<<<128, 256>>>(psum, psq, gm2, be2, bna, bnc);

    apply_out<<<(NNODES * 128) / 256, 256>>>(mx, mn, bna, bnc, out);
}